// round 14
// baseline (speedup 1.0000x reference)
#include <cuda_runtime.h>
#include <cuda_bf16.h>
#include <cstdint>

// ---------------- problem constants ----------------
#define V_REAL 50257
#define EDIM   512
#define MROWS  4096
#define TOPK   8
#define NSEL   16

// GEMM structure: persistent over N within a group
#define GN   9                      // N groups (grid.x) -> 288 CTAs (2-wave balanced)
#define TPG  44                     // tiles per group
#define BN   128                    // tile width
#define VPAD (GN*TPG*BN)            // 50688 padded vocab
#define BM   128
#define BKB  64                     // K bytes per chunk (int8)
#define NKC  (EDIM/BKB)             // 8 chunks
#define LDQ  80                     // smem row pitch bytes (64 + 16 pad, conflict-free)
#define CAND (GN*TOPK)              // 72 candidates per row

#define FLT_MAX_ 3.402823466e+38f
#define TINY_F   1.17549435e-38f
#define NORM_EPS 1e-12f

// smem: 3 stages x (A 10240 + B 10240) = 61440; int score staging 33792; escale 512
#define STAGE_BYTES 20480
#define SC_OFF      61440
#define ESC_OFF     (61440 + 33792)
#define SMEM_GEMM   (61440 + 33792 + 512)   // 95744 -> 2 CTAs/SM

// ---------------- scratch (device globals; only referenced from device code) ----------------
static __device__ int8_t g_embq [(size_t)VPAD * EDIM];   // ~26 MB
static __device__ int8_t g_projq[(size_t)MROWS * EDIM];  // 2 MB
static __device__ float  g_escale[VPAD];                 // per-embedding dequant scale
static __device__ float2 g_cand[(size_t)MROWS * CAND];   // ~2.4 MB

// ---------------- helpers ----------------
__device__ __forceinline__ void cp16(uint32_t dst, const void* src) {
    asm volatile("cp.async.cg.shared.global [%0], [%1], 16;\n" :: "r"(dst), "l"(src));
}
__device__ __forceinline__ void cp_commit() { asm volatile("cp.async.commit_group;\n" ::); }
__device__ __forceinline__ void cp_wait0()  { asm volatile("cp.async.wait_group 0;\n" ::); }
__device__ __forceinline__ void cp_wait1()  { asm volatile("cp.async.wait_group 1;\n" ::); }

__device__ __forceinline__ void ldsm4(uint32_t* r, uint32_t addr) {
    asm volatile("ldmatrix.sync.aligned.m8n8.x4.shared.b16 {%0,%1,%2,%3}, [%4];\n"
                 : "=r"(r[0]), "=r"(r[1]), "=r"(r[2]), "=r"(r[3]) : "r"(addr));
}
// int8 tensor-core MMA: D(s32) = A(s8,row) * B(s8,col) + D
__device__ __forceinline__ void imma16832(int* c, const uint32_t* a, const uint32_t* b) {
    asm volatile(
        "mma.sync.aligned.m16n8k32.row.col.s32.s8.s8.s32 "
        "{%0,%1,%2,%3}, {%4,%5,%6,%7}, {%8,%9}, {%0,%1,%2,%3};\n"
        : "+r"(c[0]), "+r"(c[1]), "+r"(c[2]), "+r"(c[3])
        : "r"(a[0]), "r"(a[1]), "r"(a[2]), "r"(a[3]), "r"(b[0]), "r"(b[1]));
}

__device__ __forceinline__ uint32_t rotl32(uint32_t v, int d) { return (v << d) | (v >> (32 - d)); }

// Exact JAX threefry2x32 (key = [0, 42])
__device__ __forceinline__ uint2 threefry2x32(uint32_t k0, uint32_t k1, uint32_t x0, uint32_t x1) {
    uint32_t ks2 = k0 ^ k1 ^ 0x1BD11BDAu;
    x0 += k0; x1 += k1;
#define TF_R4(a,b,c,d) \
    { x0 += x1; x1 = rotl32(x1,a); x1 ^= x0; \
      x0 += x1; x1 = rotl32(x1,b); x1 ^= x0; \
      x0 += x1; x1 = rotl32(x1,c); x1 ^= x0; \
      x0 += x1; x1 = rotl32(x1,d); x1 ^= x0; }
    TF_R4(13,15,26,6);  x0 += k1;  x1 += ks2 + 1u;
    TF_R4(17,29,16,24); x0 += ks2; x1 += k0  + 2u;
    TF_R4(13,15,26,6);  x0 += k0;  x1 += k1  + 3u;
    TF_R4(17,29,16,24); x0 += k1;  x1 += ks2 + 4u;
    TF_R4(13,15,26,6);  x0 += ks2; x1 += k0  + 5u;
#undef TF_R4
    return make_uint2(x0, x1);
}
// JAX partitionable random_bits (32-bit): xor-fold of both output lanes.
__device__ __forceinline__ uint32_t jax_random_bits32(uint32_t i) {
    uint2 o = threefry2x32(0u, 42u, 0u, i);
    return o.x ^ o.y;
}

// Branchless register top-8 insert (constant indices only; no local memory).
#define TOP8_INSERT(tv, ti, v, idx)                                   \
    {                                                                 \
        float _cv = (v); int _ci = (idx);                             \
        _Pragma("unroll")                                             \
        for (int _k = 0; _k < 8; _k++) {                              \
            bool _gt = _cv > tv[_k];                                  \
            float _ov = tv[_k]; int _oi = ti[_k];                     \
            tv[_k] = _gt ? _cv : tv[_k];                              \
            ti[_k] = _gt ? _ci : ti[_k];                              \
            _cv = _gt ? _ov : _cv;                                    \
            _ci = _gt ? _oi : _ci;                                    \
        }                                                             \
    }

// ---------------- kernel 1/2: row L2 normalize -> int8 quantized ----------------
// q = rint(x * 127 / max|x|); escale = max|x| / (127 * ||x||)  (emb only)
__global__ void normalize_kernel(const float* __restrict__ src, int real_rows, int which) {
    int8_t* dstq = which ? g_projq : g_embq;     // device-side symbol ref
    int r = blockIdx.x, tid = threadIdx.x;
    if (r >= real_rows) {                        // zero-pad rows (embeddings padding)
        ((uint32_t*)(dstq + (size_t)r * EDIM))[tid] = 0u;
        if (!which && tid == 0) g_escale[r] = 0.f;
        return;
    }
    float4 v = ((const float4*)(src + (size_t)r * EDIM))[tid];
    float ss = v.x * v.x + v.y * v.y + v.z * v.z + v.w * v.w;
    float am = fmaxf(fmaxf(fabsf(v.x), fabsf(v.y)), fmaxf(fabsf(v.z), fabsf(v.w)));
    #pragma unroll
    for (int o = 16; o; o >>= 1) {
        ss += __shfl_xor_sync(0xffffffffu, ss, o);
        am  = fmaxf(am, __shfl_xor_sync(0xffffffffu, am, o));
    }
    __shared__ float wsum[4], wmax[4];
    if ((tid & 31) == 0) { wsum[tid >> 5] = ss; wmax[tid >> 5] = am; }
    __syncthreads();
    float tot  = wsum[0] + wsum[1] + wsum[2] + wsum[3];
    float amax = fmaxf(fmaxf(wmax[0], wmax[1]), fmaxf(wmax[2], wmax[3]));
    amax = fmaxf(amax, 1e-20f);
    float denom = fmaxf(sqrtf(tot), NORM_EPS);
    float qs = 127.f / amax;
    char4 q;
    q.x = (char)__float2int_rn(v.x * qs);
    q.y = (char)__float2int_rn(v.y * qs);
    q.z = (char)__float2int_rn(v.z * qs);
    q.w = (char)__float2int_rn(v.w * qs);
    ((char4*)(dstq + (size_t)r * EDIM))[tid] = q;
    if (!which && tid == 0) g_escale[r] = amax / (127.f * denom);
}

// ---------------- kernel 3: persistent int8 MMA GEMM + carried top-8 ----------------
// grid (GN, 32), block 256 (8 warps: 4 over M x 2 over N, warp tile 32x64).
// 3-stage cp.async pipeline (wait_group 1); per-tile dequant via escale in epilogue.
__global__ void __launch_bounds__(256, 2) gemm_topk_kernel() {
    extern __shared__ char smem[];
    const int tid = threadIdx.x, lane = tid & 31, wid = tid >> 5;
    const int grp = blockIdx.x, bm = blockIdx.y;
    const int m0 = bm * BM;
    const int ncol0 = grp * TPG * BN;

    uint32_t sbase = (uint32_t)__cvta_generic_to_shared(smem);
    int*   sc  = (int*)(smem + SC_OFF);           // [128][66] int score staging
    float* esc = (float*)(smem + ESC_OFF);        // [128] per-tile embedding scales

    const int wm0 = (wid >> 1) * 32;     // 4 warps over M
    const int wn  = wid & 1;             // 2 warps over N
    const int wn0 = wn * 64;

    // load A+B chunk c (64 K-bytes) into stage st
    auto loadChunk = [&](int c, int st) {
        int t = c >> 3, kc = c & 7;
        uint32_t aB = sbase + st * STAGE_BYTES;
        uint32_t bB = aB + 10240;
        const int8_t* gp = g_projq + (size_t)m0 * EDIM + kc * BKB;
        const int8_t* gb = g_embq + (size_t)(ncol0 + t * BN) * EDIM + kc * BKB;
        #pragma unroll
        for (int i = 0; i < 2; i++) {
            int vId = tid + i * 256;
            int row = vId >> 2, q = vId & 3;
            cp16(aB + row * LDQ + q * 16, gp + (size_t)row * EDIM + q * 16);
            cp16(bB + row * LDQ + q * 16, gb + (size_t)row * EDIM + q * 16);
        }
    };

    // ldmatrix addressing (bytes)
    const int aRow = lane & 15;
    const int aKb  = (lane >> 4) << 4;             // 0 or 16
    const int bN   = (lane & 7) + (((lane >> 4) & 1) << 3);
    const int bKb  = ((lane >> 3) & 1) << 4;       // 0 or 16
    const int g    = lane >> 2, t4 = lane & 3;

    // carried top-8 (registers, persist across all TPG tiles)
    float tv[TOPK]; int ti[TOPK];
    #pragma unroll
    for (int k = 0; k < TOPK; k++) { tv[k] = -FLT_MAX_; ti[k] = -1; }

    const int TOT = TPG * NKC;
    loadChunk(0, 0); cp_commit();
    loadChunk(1, 1); cp_commit();

    for (int t = 0; t < TPG; t++) {
        int acc[2][8][4];
        #pragma unroll
        for (int mi = 0; mi < 2; mi++)
            #pragma unroll
            for (int ni = 0; ni < 8; ni++)
                #pragma unroll
                for (int q = 0; q < 4; q++) acc[mi][ni][q] = 0;

        for (int kc = 0; kc < NKC; kc++) {
            const int c = t * NKC + kc;
            if (c + 1 < TOT) cp_wait1(); else cp_wait0();
            __syncthreads();
            if (c + 2 < TOT) { loadChunk(c + 2, (c + 2) % 3); cp_commit(); }

            uint32_t aBase = sbase + (c % 3) * STAGE_BYTES;
            uint32_t bBase = aBase + 10240;
            #pragma unroll
            for (int s = 0; s < 2; s++) {
                uint32_t a[2][4], b[8][2];
                int kb = s * 32;                  // k32 per s-iter (32 bytes)
                #pragma unroll
                for (int mi = 0; mi < 2; mi++) {
                    uint32_t addr = aBase + (wm0 + mi * 16 + aRow) * LDQ + kb + aKb;
                    ldsm4(a[mi], addr);
                }
                #pragma unroll
                for (int p = 0; p < 4; p++) {
                    uint32_t tmp[4];
                    uint32_t addr = bBase + (wn0 + p * 16 + bN) * LDQ + kb + bKb;
                    ldsm4(tmp, addr);
                    b[2 * p][0] = tmp[0]; b[2 * p][1] = tmp[1];
                    b[2 * p + 1][0] = tmp[2]; b[2 * p + 1][1] = tmp[3];
                }
                #pragma unroll
                for (int mi = 0; mi < 2; mi++)
                    #pragma unroll
                    for (int ni = 0; ni < 8; ni++)
                        imma16832(acc[mi][ni], a[mi], b[ni]);
            }
        }

        // ---- epilogue for tile t: stage int scores, dequant by escale, carried top-8 ----
        const int tile_col0 = ncol0 + t * BN;
        #pragma unroll
        for (int h = 0; h < 2; h++) {
            __syncthreads();
            if (h == 0 && tid < 128) esc[tid] = g_escale[tile_col0 + tid];
            if (wn == h) {
                #pragma unroll
                for (int mi = 0; mi < 2; mi++)
                    #pragma unroll
                    for (int ni = 0; ni < 8; ni++) {
                        int r = wm0 + mi * 16 + g;
                        int c = ni * 8 + t4 * 2;
                        sc[r * 66 + c]           = acc[mi][ni][0];
                        sc[r * 66 + c + 1]       = acc[mi][ni][1];
                        sc[(r + 8) * 66 + c]     = acc[mi][ni][2];
                        sc[(r + 8) * 66 + c + 1] = acc[mi][ni][3];
                    }
            }
            __syncthreads();
            if (tid < 128) {
                const int* rowp = sc + tid * 66;
                int col0 = tile_col0 + h * 64;
                #pragma unroll 8
                for (int c = 0; c < 64; c++) {
                    float v = (float)rowp[c] * esc[h * 64 + c];
                    int col = col0 + c;
                    if (v > tv[TOPK - 1] && col < V_REAL) {
                        TOP8_INSERT(tv, ti, v, col);
                    }
                }
            }
        }
    }

    // write carried top-8 for this (row, group)
    if (tid < 128) {
        float2* dst = g_cand + ((size_t)(m0 + tid) * GN + grp) * TOPK;
        #pragma unroll
        for (int j = 0; j < TOPK; j++) dst[j] = make_float2(tv[j], __int_as_float(ti[j]));
    }
}

// ---------------- kernel 4: merge 72 candidates, fp32 rescore, top-8, sample ----------------
__global__ void __launch_bounds__(256) merge_sample_kernel(const float* __restrict__ proj_raw,
                                                           const float* __restrict__ emb_raw,
                                                           float* __restrict__ out) {
    __shared__ float sh_proj[EDIM];
    __shared__ float sv[CAND];
    __shared__ int   si[CAND];
    __shared__ float red_v[8];
    __shared__ int   red_p[8];
    __shared__ int   sidx[NSEL];
    __shared__ float strue[NSEL];
    __shared__ float pnorm2[8];

    const int row = blockIdx.x;
    const int tid = threadIdx.x, lane = tid & 31, wid = tid >> 5;

    // normalize raw projection row
    {
        float ss = 0.f;
        for (int j = tid; j < EDIM; j += 256) {
            float x = proj_raw[(size_t)row * EDIM + j];
            sh_proj[j] = x;
            ss += x * x;
        }
        #pragma unroll
        for (int o = 16; o; o >>= 1) ss += __shfl_xor_sync(0xffffffffu, ss, o);
        if (lane == 0) pnorm2[wid] = ss;
        __syncthreads();
        float tot = 0.f;
        #pragma unroll
        for (int w = 0; w < 8; w++) tot += pnorm2[w];
        float denom = fmaxf(sqrtf(tot), NORM_EPS);
        __syncthreads();
        for (int j = tid; j < EDIM; j += 256) sh_proj[j] = sh_proj[j] / denom;
    }
    if (tid < CAND) {
        float2 cv = g_cand[(size_t)row * CAND + tid];
        sv[tid] = cv.x; si[tid] = __float_as_int(cv.y);
    }
    __syncthreads();

    // block top-NSEL by iterative argmax over the CAND candidates
    for (int it = 0; it < NSEL; it++) {
        float bv = -FLT_MAX_; int bp = 0;
        if (tid < CAND) { bv = sv[tid]; bp = tid; }
        #pragma unroll
        for (int o = 16; o; o >>= 1) {
            float ov = __shfl_down_sync(0xffffffffu, bv, o);
            int   op = __shfl_down_sync(0xffffffffu, bp, o);
            if (ov > bv) { bv = ov; bp = op; }
        }
        if (lane == 0) { red_v[wid] = bv; red_p[wid] = bp; }
        __syncthreads();
        if (tid == 0) {
            float m = red_v[0]; int p = red_p[0];
            #pragma unroll
            for (int w = 1; w < 8; w++) if (red_v[w] > m) { m = red_v[w]; p = red_p[w]; }
            sidx[it] = si[p];
            sv[p] = -FLT_MAX_;
        }
        __syncthreads();
    }

    // exact fp32 rescore: s = <proj_n, emb_raw[idx]> / max(||emb_raw[idx]||, eps)
    for (int c = wid; c < NSEL; c += 8) {
        int idx = sidx[c];
        float s = 0.f, e2 = 0.f;
        if (idx >= 0) {
            const float* e = emb_raw + (size_t)idx * EDIM;
            for (int j = lane; j < EDIM; j += 32) {
                float ev = e[j];
                s  = fmaf(sh_proj[j], ev, s);
                e2 = fmaf(ev, ev, e2);
            }
        }
        #pragma unroll
        for (int o = 16; o; o >>= 1) {
            s  += __shfl_xor_sync(0xffffffffu, s, o);
            e2 += __shfl_xor_sync(0xffffffffu, e2, o);
        }
        if (lane == 0) strue[c] = (idx >= 0) ? s / fmaxf(sqrtf(e2), NORM_EPS) : -FLT_MAX_;
    }
    __syncthreads();

    if (tid == 0) {
        // stable top-8: val desc, index asc (matches lax.top_k)
        float fv[TOPK]; int fi[TOPK];
        unsigned used = 0;
        for (int r = 0; r < TOPK; r++) {
            int best = -1; float bv = 0.f; int bi = 0;
            for (int c = 0; c < NSEL; c++) {
                if ((used >> c) & 1u) continue;
                float v = strue[c]; int ix = sidx[c];
                if (best < 0 || v > bv || (v == bv && ix < bi)) { best = c; bv = v; bi = ix; }
            }
            used |= 1u << best;
            fv[r] = bv; fi[r] = bi;
        }
        // gumbel-argmax sampling (partitionable threefry, xor-fold)
        float m = -FLT_MAX_; int arg = 0;
        #pragma unroll
        for (int k = 0; k < TOPK; k++) {
            unsigned i = (unsigned)row * TOPK + k;
            unsigned bits = jax_random_bits32(i);
            float f = __uint_as_float((bits >> 9) | 0x3f800000u) - 1.0f;
            float u = fmaxf(TINY_F, f);
            float gmb = -logf(-logf(u));
            float t = fv[k] + gmb;
            if (t > m) { m = t; arg = k; }
        }
        out[row] = (float)fi[arg];
    }
}

// ---------------- launcher ----------------
extern "C" void kernel_launch(void* const* d_in, const int* in_sizes, int n_in,
                              void* d_out, int out_size) {
    int ie = 0, ip = 0;
    long b1 = -1, b2 = -1;
    for (int i = 0; i < n_in; i++) {
        long s = in_sizes[i];
        if (s > b1)      { b2 = b1; ip = ie; b1 = s; ie = i; }
        else if (s > b2) { b2 = s; ip = i; }
    }
    const float* emb  = (const float*)d_in[ie];   // [50257,512]
    const float* proj = (const float*)d_in[ip];   // [4,1024,512]
    float* out = (float*)d_out;                   // [4,1024] float32 token ids

    cudaFuncSetAttribute(gemm_topk_kernel,
                         cudaFuncAttributeMaxDynamicSharedMemorySize, SMEM_GEMM);

    normalize_kernel<<<VPAD, 128>>>(emb, V_REAL, /*which=*/0);
    normalize_kernel<<<MROWS, 128>>>(proj, MROWS, /*which=*/1);
    gemm_topk_kernel<<<dim3(GN, 32), 256, SMEM_GEMM>>>();
    merge_sample_kernel<<<MROWS, 256>>>(proj, emb, out);
}

// round 15
// speedup vs baseline: 1.6163x; 1.6163x over previous
#include <cuda_runtime.h>
#include <cuda_bf16.h>
#include <cstdint>

// ---------------- problem constants ----------------
#define V_REAL 50257
#define EDIM   512
#define MROWS  4096
#define TOPK   8
#define NSEL   16

// GEMM structure: persistent over N within a group; single-wave grid
#define GN   9                      // N groups (grid.x) -> 144 CTAs (1 wave on 148 SMs)
#define TPG  44                     // tiles per group
#define BN   128                    // tile width
#define VPAD (GN*TPG*BN)            // 50688 padded vocab
#define BM   256                    // CTA M rows
#define BK   32
#define NKC  (EDIM/BK)              // 16
#define LDA  40                     // bf16 elems, padded (80B rows)
#define LDB  40
#define CAND (GN*TOPK)              // 72 candidates per row

#define FLT_MAX_ 3.402823466e+38f
#define TINY_F   1.17549435e-38f
#define NORM_EPS 1e-12f

// smem: 3 stages x (A 256*80=20480 + B 128*80=10240) = 92160; sc[256][66] = 67584
#define STAGE_BYTES 30720
#define SC_OFF      92160
#define SMEM_GEMM   (92160 + 67584)   // 159744 -> 1 CTA/SM

// ---------------- scratch (device globals; only referenced from device code) ----------------
static __device__ __nv_bfloat16 g_embn_bf16[(size_t)VPAD * EDIM];   // ~52 MB
static __device__ __nv_bfloat16 g_projn_bf16[(size_t)MROWS * EDIM]; // 4 MB
static __device__ float2        g_cand[(size_t)MROWS * CAND];       // ~2.4 MB

// ---------------- helpers ----------------
__device__ __forceinline__ void cp16(uint32_t dst, const void* src) {
    asm volatile("cp.async.cg.shared.global [%0], [%1], 16;\n" :: "r"(dst), "l"(src));
}
__device__ __forceinline__ void cp_commit() { asm volatile("cp.async.commit_group;\n" ::); }
__device__ __forceinline__ void cp_wait0()  { asm volatile("cp.async.wait_group 0;\n" ::); }
__device__ __forceinline__ void cp_wait1()  { asm volatile("cp.async.wait_group 1;\n" ::); }

__device__ __forceinline__ void ldsm4(uint32_t* r, uint32_t addr) {
    asm volatile("ldmatrix.sync.aligned.m8n8.x4.shared.b16 {%0,%1,%2,%3}, [%4];\n"
                 : "=r"(r[0]), "=r"(r[1]), "=r"(r[2]), "=r"(r[3]) : "r"(addr));
}
__device__ __forceinline__ void mma16816(float* c, const uint32_t* a, const uint32_t* b) {
    asm volatile(
        "mma.sync.aligned.m16n8k16.row.col.f32.bf16.bf16.f32 "
        "{%0,%1,%2,%3}, {%4,%5,%6,%7}, {%8,%9}, {%0,%1,%2,%3};\n"
        : "+f"(c[0]), "+f"(c[1]), "+f"(c[2]), "+f"(c[3])
        : "r"(a[0]), "r"(a[1]), "r"(a[2]), "r"(a[3]), "r"(b[0]), "r"(b[1]));
}

__device__ __forceinline__ uint32_t rotl32(uint32_t v, int d) { return (v << d) | (v >> (32 - d)); }

// Exact JAX threefry2x32 (key = [0, 42])
__device__ __forceinline__ uint2 threefry2x32(uint32_t k0, uint32_t k1, uint32_t x0, uint32_t x1) {
    uint32_t ks2 = k0 ^ k1 ^ 0x1BD11BDAu;
    x0 += k0; x1 += k1;
#define TF_R4(a,b,c,d) \
    { x0 += x1; x1 = rotl32(x1,a); x1 ^= x0; \
      x0 += x1; x1 = rotl32(x1,b); x1 ^= x0; \
      x0 += x1; x1 = rotl32(x1,c); x1 ^= x0; \
      x0 += x1; x1 = rotl32(x1,d); x1 ^= x0; }
    TF_R4(13,15,26,6);  x0 += k1;  x1 += ks2 + 1u;
    TF_R4(17,29,16,24); x0 += ks2; x1 += k0  + 2u;
    TF_R4(13,15,26,6);  x0 += k0;  x1 += k1  + 3u;
    TF_R4(17,29,16,24); x0 += k1;  x1 += ks2 + 4u;
    TF_R4(13,15,26,6);  x0 += ks2; x1 += k0  + 5u;
#undef TF_R4
    return make_uint2(x0, x1);
}
// JAX partitionable random_bits (32-bit): xor-fold of both output lanes.
__device__ __forceinline__ uint32_t jax_random_bits32(uint32_t i) {
    uint2 o = threefry2x32(0u, 42u, 0u, i);
    return o.x ^ o.y;
}

// Branchless register top-8 insert (constant indices only; no local memory).
#define TOP8_INSERT(tv, ti, v, idx)                                   \
    {                                                                 \
        float _cv = (v); int _ci = (idx);                             \
        _Pragma("unroll")                                             \
        for (int _k = 0; _k < 8; _k++) {                              \
            bool _gt = _cv > tv[_k];                                  \
            float _ov = tv[_k]; int _oi = ti[_k];                     \
            tv[_k] = _gt ? _cv : tv[_k];                              \
            ti[_k] = _gt ? _ci : ti[_k];                              \
            _cv = _gt ? _ov : _cv;                                    \
            _ci = _gt ? _oi : _ci;                                    \
        }                                                             \
    }

// ---------------- kernel 1/2: row L2 normalize -> bf16 ----------------
__global__ void normalize_kernel(const float* __restrict__ src, int real_rows, int which) {
    __nv_bfloat16* dstb = which ? g_projn_bf16 : g_embn_bf16;   // device-side symbol ref
    int r = blockIdx.x, tid = threadIdx.x;
    if (r >= real_rows) {
        ushort4 z; z.x = z.y = z.z = z.w = 0;
        ((ushort4*)(dstb + (size_t)r * EDIM))[tid] = z;
        return;
    }
    float4 v = ((const float4*)(src + (size_t)r * EDIM))[tid];
    float ss = v.x * v.x + v.y * v.y + v.z * v.z + v.w * v.w;
    #pragma unroll
    for (int o = 16; o; o >>= 1) ss += __shfl_xor_sync(0xffffffffu, ss, o);
    __shared__ float wsum[4];
    if ((tid & 31) == 0) wsum[tid >> 5] = ss;
    __syncthreads();
    float tot = wsum[0] + wsum[1] + wsum[2] + wsum[3];
    float denom = fmaxf(sqrtf(tot), NORM_EPS);
    ushort4 b;
    b.x = __bfloat16_as_ushort(__float2bfloat16(v.x / denom));
    b.y = __bfloat16_as_ushort(__float2bfloat16(v.y / denom));
    b.z = __bfloat16_as_ushort(__float2bfloat16(v.z / denom));
    b.w = __bfloat16_as_ushort(__float2bfloat16(v.w / denom));
    ((ushort4*)(dstb + (size_t)r * EDIM))[tid] = b;
}

// ---------------- kernel 3: persistent bf16 MMA GEMM + carried top-8 ----------------
// grid (GN, 16), block 256 (8 warps: 4 over M x 2 over N, warp tile 64x64).
// CTA tile 256x128; 3-stage cp.async pipeline; carried top-8 across TPG tiles.
__global__ void __launch_bounds__(256, 1) gemm_topk_kernel() {
    extern __shared__ char smem[];
    const int tid = threadIdx.x, lane = tid & 31, wid = tid >> 5;
    const int grp = blockIdx.x, bm = blockIdx.y;
    const int m0 = bm * BM;
    const int ncol0 = grp * TPG * BN;

    uint32_t sbase = (uint32_t)__cvta_generic_to_shared(smem);
    float* sc = (float*)(smem + SC_OFF);          // [256][66] score staging

    const int wm0 = (wid >> 1) * 64;     // 4 warps over M (64 rows each)
    const int wn  = wid & 1;             // 2 warps over N
    const int wn0 = wn * 64;

    // load A+B chunk c into stage st (A: 256x32 bf16, B: 128x32 bf16)
    auto loadChunk = [&](int c, int st) {
        int t = c >> 4, kc = c & 15;
        uint32_t aB = sbase + st * STAGE_BYTES;
        uint32_t bB = aB + 20480;
        const __nv_bfloat16* gp = g_projn_bf16 + (size_t)m0 * EDIM + kc * BK;
        const __nv_bfloat16* gb = g_embn_bf16 + (size_t)(ncol0 + t * BN) * EDIM + kc * BK;
        #pragma unroll
        for (int i = 0; i < 4; i++) {                 // A: 1024 vecs / 256 thr
            int vId = tid + i * 256;
            int row = vId >> 2, q = vId & 3;
            cp16(aB + (row * LDA + q * 8) * 2, gp + (size_t)row * EDIM + q * 8);
        }
        #pragma unroll
        for (int i = 0; i < 2; i++) {                 // B: 512 vecs / 256 thr
            int vId = tid + i * 256;
            int row = vId >> 2, q = vId & 3;
            cp16(bB + (row * LDB + q * 8) * 2, gb + (size_t)row * EDIM + q * 8);
        }
    };

    const int aRow = lane & 15;                    // ldmatrix addressing
    const int aK   = (lane >> 4) << 3;
    const int bN   = (lane & 7) + (((lane >> 4) & 1) << 3);
    const int bK   = ((lane >> 3) & 1) << 3;
    const int g    = lane >> 2, t4 = lane & 3;

    // carried top-8 (registers, persist across all TPG tiles)
    float tv[TOPK]; int ti[TOPK];
    #pragma unroll
    for (int k = 0; k < TOPK; k++) { tv[k] = -FLT_MAX_; ti[k] = -1; }

    const int TOT = TPG * NKC;
    loadChunk(0, 0); cp_commit();
    loadChunk(1, 1); cp_commit();

    for (int t = 0; t < TPG; t++) {
        float acc[4][8][4];
        #pragma unroll
        for (int mi = 0; mi < 4; mi++)
            #pragma unroll
            for (int ni = 0; ni < 8; ni++)
                #pragma unroll
                for (int q = 0; q < 4; q++) acc[mi][ni][q] = 0.f;

        for (int kc = 0; kc < NKC; kc++) {
            const int c = t * NKC + kc;
            if (c + 1 < TOT) cp_wait1(); else cp_wait0();
            __syncthreads();
            if (c + 2 < TOT) { loadChunk(c + 2, (c + 2) % 3); cp_commit(); }

            uint32_t aBase = sbase + (c % 3) * STAGE_BYTES;
            uint32_t bBase = aBase + 20480;
            #pragma unroll
            for (int s = 0; s < 2; s++) {
                uint32_t a[4][4], b[8][2];
                int k16 = s * 16;
                #pragma unroll
                for (int mi = 0; mi < 4; mi++) {
                    uint32_t addr = aBase + (((wm0 + mi * 16 + aRow) * LDA) + k16 + aK) * 2;
                    ldsm4(a[mi], addr);
                }
                #pragma unroll
                for (int p = 0; p < 4; p++) {
                    uint32_t tmp[4];
                    uint32_t addr = bBase + (((wn0 + p * 16 + bN) * LDB) + k16 + bK) * 2;
                    ldsm4(tmp, addr);
                    b[2 * p][0] = tmp[0]; b[2 * p][1] = tmp[1];
                    b[2 * p + 1][0] = tmp[2]; b[2 * p + 1][1] = tmp[3];
                }
                #pragma unroll
                for (int mi = 0; mi < 4; mi++)
                    #pragma unroll
                    for (int ni = 0; ni < 8; ni++)
                        mma16816(acc[mi][ni], a[mi], b[ni]);
            }
        }

        // ---- epilogue for tile t: stage to sc (separate smem), carried top-8 scan ----
        const int tile_col0 = ncol0 + t * BN;
        #pragma unroll
        for (int h = 0; h < 2; h++) {
            __syncthreads();
            if (wn == h) {
                #pragma unroll
                for (int mi = 0; mi < 4; mi++)
                    #pragma unroll
                    for (int ni = 0; ni < 8; ni++) {
                        int r = wm0 + mi * 16 + g;
                        int c = ni * 8 + t4 * 2;
                        sc[r * 66 + c]           = acc[mi][ni][0];
                        sc[r * 66 + c + 1]       = acc[mi][ni][1];
                        sc[(r + 8) * 66 + c]     = acc[mi][ni][2];
                        sc[(r + 8) * 66 + c + 1] = acc[mi][ni][3];
                    }
            }
            __syncthreads();
            {
                const float* rowp = sc + tid * 66;
                int col0 = tile_col0 + h * 64;
                #pragma unroll 8
                for (int c = 0; c < 64; c++) {
                    float v = rowp[c];
                    int col = col0 + c;
                    if (v > tv[TOPK - 1] && col < V_REAL) {
                        TOP8_INSERT(tv, ti, v, col);
                    }
                }
            }
        }
    }

    // write carried top-8 for this (row, group); tid indexes the 256 rows
    {
        float2* dst = g_cand + ((size_t)(m0 + tid) * GN + grp) * TOPK;
        #pragma unroll
        for (int j = 0; j < TOPK; j++) dst[j] = make_float2(tv[j], __int_as_float(ti[j]));
    }
}

// ---------------- kernel 4: merge 72 candidates, fp32 rescore, top-8, sample ----------------
__global__ void __launch_bounds__(256) merge_sample_kernel(const float* __restrict__ proj_raw,
                                                           const float* __restrict__ emb_raw,
                                                           float* __restrict__ out) {
    __shared__ float sh_proj[EDIM];
    __shared__ float sv[CAND];
    __shared__ int   si[CAND];
    __shared__ float red_v[8];
    __shared__ int   red_p[8];
    __shared__ int   sidx[NSEL];
    __shared__ float strue[NSEL];
    __shared__ float pnorm2[8];

    const int row = blockIdx.x;
    const int tid = threadIdx.x, lane = tid & 31, wid = tid >> 5;

    // normalize raw projection row
    {
        float ss = 0.f;
        for (int j = tid; j < EDIM; j += 256) {
            float x = proj_raw[(size_t)row * EDIM + j];
            sh_proj[j] = x;
            ss += x * x;
        }
        #pragma unroll
        for (int o = 16; o; o >>= 1) ss += __shfl_xor_sync(0xffffffffu, ss, o);
        if (lane == 0) pnorm2[wid] = ss;
        __syncthreads();
        float tot = 0.f;
        #pragma unroll
        for (int w = 0; w < 8; w++) tot += pnorm2[w];
        float denom = fmaxf(sqrtf(tot), NORM_EPS);
        __syncthreads();
        for (int j = tid; j < EDIM; j += 256) sh_proj[j] = sh_proj[j] / denom;
    }
    if (tid < CAND) {
        float2 cv = g_cand[(size_t)row * CAND + tid];
        sv[tid] = cv.x; si[tid] = __float_as_int(cv.y);
    }
    __syncthreads();

    // block top-NSEL by iterative argmax over the CAND candidates
    for (int it = 0; it < NSEL; it++) {
        float bv = -FLT_MAX_; int bp = 0;
        if (tid < CAND) { bv = sv[tid]; bp = tid; }
        #pragma unroll
        for (int o = 16; o; o >>= 1) {
            float ov = __shfl_down_sync(0xffffffffu, bv, o);
            int   op = __shfl_down_sync(0xffffffffu, bp, o);
            if (ov > bv) { bv = ov; bp = op; }
        }
        if (lane == 0) { red_v[wid] = bv; red_p[wid] = bp; }
        __syncthreads();
        if (tid == 0) {
            float m = red_v[0]; int p = red_p[0];
            #pragma unroll
            for (int w = 1; w < 8; w++) if (red_v[w] > m) { m = red_v[w]; p = red_p[w]; }
            sidx[it] = si[p];
            sv[p] = -FLT_MAX_;
        }
        __syncthreads();
    }

    // exact fp32 rescore: s = <proj_n, emb_raw[idx]> / max(||emb_raw[idx]||, eps)
    for (int c = wid; c < NSEL; c += 8) {
        int idx = sidx[c];
        float s = 0.f, e2 = 0.f;
        if (idx >= 0) {
            const float* e = emb_raw + (size_t)idx * EDIM;
            for (int j = lane; j < EDIM; j += 32) {
                float ev = e[j];
                s  = fmaf(sh_proj[j], ev, s);
                e2 = fmaf(ev, ev, e2);
            }
        }
        #pragma unroll
        for (int o = 16; o; o >>= 1) {
            s  += __shfl_xor_sync(0xffffffffu, s, o);
            e2 += __shfl_xor_sync(0xffffffffu, e2, o);
        }
        if (lane == 0) strue[c] = (idx >= 0) ? s / fmaxf(sqrtf(e2), NORM_EPS) : -FLT_MAX_;
    }
    __syncthreads();

    if (tid == 0) {
        // stable top-8: val desc, index asc (matches lax.top_k)
        float fv[TOPK]; int fi[TOPK];
        unsigned used = 0;
        for (int r = 0; r < TOPK; r++) {
            int best = -1; float bv = 0.f; int bi = 0;
            for (int c = 0; c < NSEL; c++) {
                if ((used >> c) & 1u) continue;
                float v = strue[c]; int ix = sidx[c];
                if (best < 0 || v > bv || (v == bv && ix < bi)) { best = c; bv = v; bi = ix; }
            }
            used |= 1u << best;
            fv[r] = bv; fi[r] = bi;
        }
        // gumbel-argmax sampling (partitionable threefry, xor-fold)
        float m = -FLT_MAX_; int arg = 0;
        #pragma unroll
        for (int k = 0; k < TOPK; k++) {
            unsigned i = (unsigned)row * TOPK + k;
            unsigned bits = jax_random_bits32(i);
            float f = __uint_as_float((bits >> 9) | 0x3f800000u) - 1.0f;
            float u = fmaxf(TINY_F, f);
            float gmb = -logf(-logf(u));
            float t = fv[k] + gmb;
            if (t > m) { m = t; arg = k; }
        }
        out[row] = (float)fi[arg];
    }
}

// ---------------- launcher ----------------
extern "C" void kernel_launch(void* const* d_in, const int* in_sizes, int n_in,
                              void* d_out, int out_size) {
    int ie = 0, ip = 0;
    long b1 = -1, b2 = -1;
    for (int i = 0; i < n_in; i++) {
        long s = in_sizes[i];
        if (s > b1)      { b2 = b1; ip = ie; b1 = s; ie = i; }
        else if (s > b2) { b2 = s; ip = i; }
    }
    const float* emb  = (const float*)d_in[ie];   // [50257,512]
    const float* proj = (const float*)d_in[ip];   // [4,1024,512]
    float* out = (float*)d_out;                   // [4,1024] float32 token ids

    cudaFuncSetAttribute(gemm_topk_kernel,
                         cudaFuncAttributeMaxDynamicSharedMemorySize, SMEM_GEMM);

    normalize_kernel<<<VPAD, 128>>>(emb, V_REAL, /*which=*/0);
    normalize_kernel<<<MROWS, 128>>>(proj, MROWS, /*which=*/1);
    gemm_topk_kernel<<<dim3(GN, 16), 256, SMEM_GEMM>>>();
    merge_sample_kernel<<<MROWS, 256>>>(proj, emb, out);
}

// round 16
// speedup vs baseline: 1.8709x; 1.1575x over previous
#include <cuda_runtime.h>
#include <cuda_bf16.h>
#include <cstdint>

// ---------------- problem constants ----------------
#define V_REAL 50257
#define EDIM   512
#define MROWS  4096
#define TOPK   8
#define NSEL   16

// GEMM structure: persistent over N within a group
#define GN   9                      // N groups (grid.x) -> 288 CTAs (2-wave balanced)
#define TPG  44                     // tiles per group
#define BN   128                    // tile width
#define VPAD (GN*TPG*BN)            // 50688 padded vocab
#define BM   128
#define BK   32
#define NKC  (EDIM/BK)              // 16
#define LDA  40                     // bf16 elems, padded (80B rows)
#define LDB  40
#define CAND (GN*16)                // 144 candidates per row (2 slices x 8 per group)

#define FLT_MAX_ 3.402823466e+38f
#define TINY_F   1.17549435e-38f
#define NORM_EPS 1e-12f

// smem: 4 pipeline stages x (A 10240 + B 10240) = 81920; score staging 33792
#define STAGE_BYTES 20480
#define NSTAGE      4
#define SC_OFF      81920
#define SMEM_GEMM   (81920 + 33792)   // 115712 -> 2 CTAs/SM (231.4KB <= 233.5KB)

// ---------------- scratch (device globals; only referenced from device code) ----------------
static __device__ __nv_bfloat16 g_embn_bf16[(size_t)VPAD * EDIM];   // ~52 MB
static __device__ __nv_bfloat16 g_projn_bf16[(size_t)MROWS * EDIM]; // 4 MB
static __device__ float2        g_cand[(size_t)MROWS * CAND];       // ~4.7 MB

// ---------------- helpers ----------------
__device__ __forceinline__ void cp16(uint32_t dst, const void* src) {
    asm volatile("cp.async.cg.shared.global [%0], [%1], 16;\n" :: "r"(dst), "l"(src));
}
__device__ __forceinline__ void cp_commit() { asm volatile("cp.async.commit_group;\n" ::); }
__device__ __forceinline__ void cp_wait0()  { asm volatile("cp.async.wait_group 0;\n" ::); }
__device__ __forceinline__ void cp_wait2()  { asm volatile("cp.async.wait_group 2;\n" ::); }

__device__ __forceinline__ void ldsm4(uint32_t* r, uint32_t addr) {
    asm volatile("ldmatrix.sync.aligned.m8n8.x4.shared.b16 {%0,%1,%2,%3}, [%4];\n"
                 : "=r"(r[0]), "=r"(r[1]), "=r"(r[2]), "=r"(r[3]) : "r"(addr));
}
__device__ __forceinline__ void mma16816(float* c, const uint32_t* a, const uint32_t* b) {
    asm volatile(
        "mma.sync.aligned.m16n8k16.row.col.f32.bf16.bf16.f32 "
        "{%0,%1,%2,%3}, {%4,%5,%6,%7}, {%8,%9}, {%0,%1,%2,%3};\n"
        : "+f"(c[0]), "+f"(c[1]), "+f"(c[2]), "+f"(c[3])
        : "r"(a[0]), "r"(a[1]), "r"(a[2]), "r"(a[3]), "r"(b[0]), "r"(b[1]));
}

__device__ __forceinline__ uint32_t rotl32(uint32_t v, int d) { return (v << d) | (v >> (32 - d)); }

// Exact JAX threefry2x32 (key = [0, 42])
__device__ __forceinline__ uint2 threefry2x32(uint32_t k0, uint32_t k1, uint32_t x0, uint32_t x1) {
    uint32_t ks2 = k0 ^ k1 ^ 0x1BD11BDAu;
    x0 += k0; x1 += k1;
#define TF_R4(a,b,c,d) \
    { x0 += x1; x1 = rotl32(x1,a); x1 ^= x0; \
      x0 += x1; x1 = rotl32(x1,b); x1 ^= x0; \
      x0 += x1; x1 = rotl32(x1,c); x1 ^= x0; \
      x0 += x1; x1 = rotl32(x1,d); x1 ^= x0; }
    TF_R4(13,15,26,6);  x0 += k1;  x1 += ks2 + 1u;
    TF_R4(17,29,16,24); x0 += ks2; x1 += k0  + 2u;
    TF_R4(13,15,26,6);  x0 += k0;  x1 += k1  + 3u;
    TF_R4(17,29,16,24); x0 += k1;  x1 += ks2 + 4u;
    TF_R4(13,15,26,6);  x0 += ks2; x1 += k0  + 5u;
#undef TF_R4
    return make_uint2(x0, x1);
}
// JAX partitionable random_bits (32-bit): xor-fold of both output lanes.
__device__ __forceinline__ uint32_t jax_random_bits32(uint32_t i) {
    uint2 o = threefry2x32(0u, 42u, 0u, i);
    return o.x ^ o.y;
}

// Branchless register top-8 insert (constant indices only; no local memory).
#define TOP8_INSERT(tv, ti, v, idx)                                   \
    {                                                                 \
        float _cv = (v); int _ci = (idx);                             \
        _Pragma("unroll")                                             \
        for (int _k = 0; _k < 8; _k++) {                              \
            bool _gt = _cv > tv[_k];                                  \
            float _ov = tv[_k]; int _oi = ti[_k];                     \
            tv[_k] = _gt ? _cv : tv[_k];                              \
            ti[_k] = _gt ? _ci : ti[_k];                              \
            _cv = _gt ? _ov : _cv;                                    \
            _ci = _gt ? _oi : _ci;                                    \
        }                                                             \
    }

// ---------------- kernel 1/2: row L2 normalize -> bf16 ----------------
__global__ void normalize_kernel(const float* __restrict__ src, int real_rows, int which) {
    __nv_bfloat16* dstb = which ? g_projn_bf16 : g_embn_bf16;   // device-side symbol ref
    int r = blockIdx.x, tid = threadIdx.x;
    if (r >= real_rows) {
        ushort4 z; z.x = z.y = z.z = z.w = 0;
        ((ushort4*)(dstb + (size_t)r * EDIM))[tid] = z;
        return;
    }
    float4 v = ((const float4*)(src + (size_t)r * EDIM))[tid];
    float ss = v.x * v.x + v.y * v.y + v.z * v.z + v.w * v.w;
    #pragma unroll
    for (int o = 16; o; o >>= 1) ss += __shfl_xor_sync(0xffffffffu, ss, o);
    __shared__ float wsum[4];
    if ((tid & 31) == 0) wsum[tid >> 5] = ss;
    __syncthreads();
    float tot = wsum[0] + wsum[1] + wsum[2] + wsum[3];
    float denom = fmaxf(sqrtf(tot), NORM_EPS);
    ushort4 b;
    b.x = __bfloat16_as_ushort(__float2bfloat16(v.x / denom));
    b.y = __bfloat16_as_ushort(__float2bfloat16(v.y / denom));
    b.z = __bfloat16_as_ushort(__float2bfloat16(v.z / denom));
    b.w = __bfloat16_as_ushort(__float2bfloat16(v.w / denom));
    ((ushort4*)(dstb + (size_t)r * EDIM))[tid] = b;
}

// ---------------- kernel 3: persistent bf16 MMA GEMM + carried top-8 ----------------
// grid (GN, 32), block 256 (8 warps: 4 over M x 2 over N, warp tile 32x64).
// 4-stage cp.async pipeline (wait_group 2); epilogue: 256 threads scan 32 cols each.
__global__ void __launch_bounds__(256, 2) gemm_topk_kernel() {
    extern __shared__ char smem[];
    const int tid = threadIdx.x, lane = tid & 31, wid = tid >> 5;
    const int grp = blockIdx.x, bm = blockIdx.y;
    const int m0 = bm * BM;
    const int ncol0 = grp * TPG * BN;

    uint32_t sbase = (uint32_t)__cvta_generic_to_shared(smem);
    float* sc = (float*)(smem + SC_OFF);          // [128][66] score staging

    const int wm0 = (wid >> 1) * 32;     // 4 warps over M
    const int wn  = wid & 1;             // 2 warps over N
    const int wn0 = wn * 64;

    // load A+B chunk c into stage st
    auto loadChunk = [&](int c, int st) {
        int t = c >> 4, kc = c & 15;
        uint32_t aB = sbase + st * STAGE_BYTES;
        uint32_t bB = aB + 10240;
        const __nv_bfloat16* gp = g_projn_bf16 + (size_t)m0 * EDIM + kc * BK;
        const __nv_bfloat16* gb = g_embn_bf16 + (size_t)(ncol0 + t * BN) * EDIM + kc * BK;
        #pragma unroll
        for (int i = 0; i < 2; i++) {
            int vId = tid + i * 256;
            int row = vId >> 2, q = vId & 3;
            cp16(aB + (row * LDA + q * 8) * 2, gp + (size_t)row * EDIM + q * 8);
            cp16(bB + (row * LDB + q * 8) * 2, gb + (size_t)row * EDIM + q * 8);
        }
    };

    const int aRow = lane & 15;                    // ldmatrix addressing
    const int aK   = (lane >> 4) << 3;
    const int bN   = (lane & 7) + (((lane >> 4) & 1) << 3);
    const int bK   = ((lane >> 3) & 1) << 3;
    const int g    = lane >> 2, t4 = lane & 3;

    // epilogue partition: thread scans row (tid&127), cols [(tid>>7)*32, +32) of each half
    const int erow  = tid & 127;
    const int eoff  = (tid >> 7) * 32;

    // carried top-8 (registers, persist across all TPG tiles; per (row, col-slice))
    float tv[TOPK]; int ti[TOPK];
    #pragma unroll
    for (int k = 0; k < TOPK; k++) { tv[k] = -FLT_MAX_; ti[k] = -1; }

    const int TOT = TPG * NKC;
    loadChunk(0, 0); cp_commit();
    loadChunk(1, 1); cp_commit();
    loadChunk(2, 2); cp_commit();

    for (int t = 0; t < TPG; t++) {
        float acc[2][8][4];
        #pragma unroll
        for (int mi = 0; mi < 2; mi++)
            #pragma unroll
            for (int ni = 0; ni < 8; ni++)
                #pragma unroll
                for (int q = 0; q < 4; q++) acc[mi][ni][q] = 0.f;

        for (int kc = 0; kc < NKC; kc++) {
            const int c = t * NKC + kc;
            if (c + 2 < TOT) cp_wait2(); else cp_wait0();
            __syncthreads();
            if (c + 3 < TOT) { loadChunk(c + 3, (c + 3) % NSTAGE); cp_commit(); }

            uint32_t aBase = sbase + (c % NSTAGE) * STAGE_BYTES;
            uint32_t bBase = aBase + 10240;
            #pragma unroll
            for (int s = 0; s < 2; s++) {
                uint32_t a[2][4], b[8][2];
                int k16 = s * 16;
                #pragma unroll
                for (int mi = 0; mi < 2; mi++) {
                    uint32_t addr = aBase + (((wm0 + mi * 16 + aRow) * LDA) + k16 + aK) * 2;
                    ldsm4(a[mi], addr);
                }
                #pragma unroll
                for (int p = 0; p < 4; p++) {
                    uint32_t tmp[4];
                    uint32_t addr = bBase + (((wn0 + p * 16 + bN) * LDB) + k16 + bK) * 2;
                    ldsm4(tmp, addr);
                    b[2 * p][0] = tmp[0]; b[2 * p][1] = tmp[1];
                    b[2 * p + 1][0] = tmp[2]; b[2 * p + 1][1] = tmp[3];
                }
                #pragma unroll
                for (int mi = 0; mi < 2; mi++)
                    #pragma unroll
                    for (int ni = 0; ni < 8; ni++)
                        mma16816(acc[mi][ni], a[mi], b[ni]);
            }
        }

        // ---- epilogue for tile t: stage halves, all 256 threads scan 32 cols each ----
        const int tile_col0 = ncol0 + t * BN;
        #pragma unroll
        for (int h = 0; h < 2; h++) {
            __syncthreads();
            if (wn == h) {
                #pragma unroll
                for (int mi = 0; mi < 2; mi++)
                    #pragma unroll
                    for (int ni = 0; ni < 8; ni++) {
                        int r = wm0 + mi * 16 + g;
                        int c = ni * 8 + t4 * 2;
                        sc[r * 66 + c]           = acc[mi][ni][0];
                        sc[r * 66 + c + 1]       = acc[mi][ni][1];
                        sc[(r + 8) * 66 + c]     = acc[mi][ni][2];
                        sc[(r + 8) * 66 + c + 1] = acc[mi][ni][3];
                    }
            }
            __syncthreads();
            {
                const float* rowp = sc + erow * 66 + eoff;
                int col0 = tile_col0 + h * 64 + eoff;
                #pragma unroll 8
                for (int c = 0; c < 32; c++) {
                    float v = rowp[c];
                    int col = col0 + c;
                    if (v > tv[TOPK - 1] && col < V_REAL) {
                        TOP8_INSERT(tv, ti, v, col);
                    }
                }
            }
        }
    }

    // write carried top-8 for this (row, group, slice)
    {
        float2* dst = g_cand + ((size_t)(m0 + erow) * GN + grp) * 16 + (tid >> 7) * 8;
        #pragma unroll
        for (int j = 0; j < TOPK; j++) dst[j] = make_float2(tv[j], __int_as_float(ti[j]));
    }
}

// ---------------- kernel 4: merge 144 candidates, fp32 rescore, top-8, sample ----------------
__global__ void __launch_bounds__(256) merge_sample_kernel(const float* __restrict__ proj_raw,
                                                           const float* __restrict__ emb_raw,
                                                           float* __restrict__ out) {
    __shared__ float sh_proj[EDIM];
    __shared__ float sv[CAND];
    __shared__ int   si[CAND];
    __shared__ float red_v[8];
    __shared__ int   red_p[8];
    __shared__ int   sidx[NSEL];
    __shared__ float strue[NSEL];
    __shared__ float pnorm2[8];

    const int row = blockIdx.x;
    const int tid = threadIdx.x, lane = tid & 31, wid = tid >> 5;

    // normalize raw projection row
    {
        float ss = 0.f;
        for (int j = tid; j < EDIM; j += 256) {
            float x = proj_raw[(size_t)row * EDIM + j];
            sh_proj[j] = x;
            ss += x * x;
        }
        #pragma unroll
        for (int o = 16; o; o >>= 1) ss += __shfl_xor_sync(0xffffffffu, ss, o);
        if (lane == 0) pnorm2[wid] = ss;
        __syncthreads();
        float tot = 0.f;
        #pragma unroll
        for (int w = 0; w < 8; w++) tot += pnorm2[w];
        float denom = fmaxf(sqrtf(tot), NORM_EPS);
        __syncthreads();
        for (int j = tid; j < EDIM; j += 256) sh_proj[j] = sh_proj[j] / denom;
    }
    if (tid < CAND) {
        float2 cv = g_cand[(size_t)row * CAND + tid];
        sv[tid] = cv.x; si[tid] = __float_as_int(cv.y);
    }
    __syncthreads();

    // block top-NSEL by iterative argmax over the CAND candidates
    for (int it = 0; it < NSEL; it++) {
        float bv = -FLT_MAX_; int bp = 0;
        if (tid < CAND) { bv = sv[tid]; bp = tid; }
        #pragma unroll
        for (int o = 16; o; o >>= 1) {
            float ov = __shfl_down_sync(0xffffffffu, bv, o);
            int   op = __shfl_down_sync(0xffffffffu, bp, o);
            if (ov > bv) { bv = ov; bp = op; }
        }
        if (lane == 0) { red_v[wid] = bv; red_p[wid] = bp; }
        __syncthreads();
        if (tid == 0) {
            float m = red_v[0]; int p = red_p[0];
            #pragma unroll
            for (int w = 1; w < 8; w++) if (red_v[w] > m) { m = red_v[w]; p = red_p[w]; }
            sidx[it] = si[p];
            sv[p] = -FLT_MAX_;
        }
        __syncthreads();
    }

    // exact fp32 rescore: s = <proj_n, emb_raw[idx]> / max(||emb_raw[idx]||, eps)
    for (int c = wid; c < NSEL; c += 8) {
        int idx = sidx[c];
        float s = 0.f, e2 = 0.f;
        if (idx >= 0) {
            const float* e = emb_raw + (size_t)idx * EDIM;
            for (int j = lane; j < EDIM; j += 32) {
                float ev = e[j];
                s  = fmaf(sh_proj[j], ev, s);
                e2 = fmaf(ev, ev, e2);
            }
        }
        #pragma unroll
        for (int o = 16; o; o >>= 1) {
            s  += __shfl_xor_sync(0xffffffffu, s, o);
            e2 += __shfl_xor_sync(0xffffffffu, e2, o);
        }
        if (lane == 0) strue[c] = (idx >= 0) ? s / fmaxf(sqrtf(e2), NORM_EPS) : -FLT_MAX_;
    }
    __syncthreads();

    if (tid == 0) {
        // stable top-8: val desc, index asc (matches lax.top_k)
        float fv[TOPK]; int fi[TOPK];
        unsigned used = 0;
        for (int r = 0; r < TOPK; r++) {
            int best = -1; float bv = 0.f; int bi = 0;
            for (int c = 0; c < NSEL; c++) {
                if ((used >> c) & 1u) continue;
                float v = strue[c]; int ix = sidx[c];
                if (best < 0 || v > bv || (v == bv && ix < bi)) { best = c; bv = v; bi = ix; }
            }
            used |= 1u << best;
            fv[r] = bv; fi[r] = bi;
        }
        // gumbel-argmax sampling (partitionable threefry, xor-fold)
        float m = -FLT_MAX_; int arg = 0;
        #pragma unroll
        for (int k = 0; k < TOPK; k++) {
            unsigned i = (unsigned)row * TOPK + k;
            unsigned bits = jax_random_bits32(i);
            float f = __uint_as_float((bits >> 9) | 0x3f800000u) - 1.0f;
            float u = fmaxf(TINY_F, f);
            float gmb = -logf(-logf(u));
            float t = fv[k] + gmb;
            if (t > m) { m = t; arg = k; }
        }
        out[row] = (float)fi[arg];
    }
}

// ---------------- launcher ----------------
extern "C" void kernel_launch(void* const* d_in, const int* in_sizes, int n_in,
                              void* d_out, int out_size) {
    int ie = 0, ip = 0;
    long b1 = -1, b2 = -1;
    for (int i = 0; i < n_in; i++) {
        long s = in_sizes[i];
        if (s > b1)      { b2 = b1; ip = ie; b1 = s; ie = i; }
        else if (s > b2) { b2 = s; ip = i; }
    }
    const float* emb  = (const float*)d_in[ie];   // [50257,512]
    const float* proj = (const float*)d_in[ip];   // [4,1024,512]
    float* out = (float*)d_out;                   // [4,1024] float32 token ids

    cudaFuncSetAttribute(gemm_topk_kernel,
                         cudaFuncAttributeMaxDynamicSharedMemorySize, SMEM_GEMM);

    normalize_kernel<<<VPAD, 128>>>(emb, V_REAL, /*which=*/0);
    normalize_kernel<<<MROWS, 128>>>(proj, MROWS, /*which=*/1);
    gemm_topk_kernel<<<dim3(GN, 32), 256, SMEM_GEMM>>>();
    merge_sample_kernel<<<MROWS, 256>>>(proj, emb, out);
}

// round 17
// speedup vs baseline: 1.8809x; 1.0054x over previous
#include <cuda_runtime.h>
#include <cuda_bf16.h>
#include <cstdint>

// ---------------- problem constants ----------------
#define V_REAL 50257
#define EDIM   512
#define MROWS  4096
#define TOPK   8
#define NSEL   16

// GEMM structure: persistent over N within a group
#define GN   9                      // N groups (grid.x) -> 288 CTAs (2-wave balanced)
#define TPG  44                     // tiles per group
#define BN   128                    // tile width
#define VPAD (GN*TPG*BN)            // 50688 padded vocab
#define BM   128
#define BK   32
#define NKC  (EDIM/BK)              // 16
#define LDA  40                     // bf16 elems, padded (80B rows)
#define LDB  40
#define CAND (GN*16)                // 144 candidates per row (2 slices x 8 per group)

#define FLT_MAX_ 3.402823466e+38f
#define TINY_F   1.17549435e-38f
#define NORM_EPS 1e-12f

// smem: 4 pipeline stages x (A 10240 + B 10240) = 81920; score staging 33792
#define STAGE_BYTES 20480
#define NSTAGE      4
#define SC_OFF      81920
#define SMEM_GEMM   (81920 + 33792)   // 115712 -> 2 CTAs/SM

// ---------------- scratch (device globals; only referenced from device code) ----------------
static __device__ __nv_bfloat16 g_embn_bf16[(size_t)VPAD * EDIM];   // ~52 MB
static __device__ __nv_bfloat16 g_projn_bf16[(size_t)MROWS * EDIM]; // 4 MB
static __device__ float2        g_cand[(size_t)MROWS * CAND];       // ~4.7 MB

// ---------------- helpers ----------------
__device__ __forceinline__ void cp16(uint32_t dst, const void* src) {
    asm volatile("cp.async.cg.shared.global [%0], [%1], 16;\n" :: "r"(dst), "l"(src));
}
__device__ __forceinline__ void cp_commit() { asm volatile("cp.async.commit_group;\n" ::); }
__device__ __forceinline__ void cp_wait0()  { asm volatile("cp.async.wait_group 0;\n" ::); }
__device__ __forceinline__ void cp_wait2()  { asm volatile("cp.async.wait_group 2;\n" ::); }

__device__ __forceinline__ void ldsm4(uint32_t* r, uint32_t addr) {
    asm volatile("ldmatrix.sync.aligned.m8n8.x4.shared.b16 {%0,%1,%2,%3}, [%4];\n"
                 : "=r"(r[0]), "=r"(r[1]), "=r"(r[2]), "=r"(r[3]) : "r"(addr));
}
__device__ __forceinline__ void mma16816(float* c, const uint32_t* a, const uint32_t* b) {
    asm volatile(
        "mma.sync.aligned.m16n8k16.row.col.f32.bf16.bf16.f32 "
        "{%0,%1,%2,%3}, {%4,%5,%6,%7}, {%8,%9}, {%0,%1,%2,%3};\n"
        : "+f"(c[0]), "+f"(c[1]), "+f"(c[2]), "+f"(c[3])
        : "r"(a[0]), "r"(a[1]), "r"(a[2]), "r"(a[3]), "r"(b[0]), "r"(b[1]));
}

__device__ __forceinline__ uint32_t rotl32(uint32_t v, int d) { return (v << d) | (v >> (32 - d)); }

// Exact JAX threefry2x32 (key = [0, 42])
__device__ __forceinline__ uint2 threefry2x32(uint32_t k0, uint32_t k1, uint32_t x0, uint32_t x1) {
    uint32_t ks2 = k0 ^ k1 ^ 0x1BD11BDAu;
    x0 += k0; x1 += k1;
#define TF_R4(a,b,c,d) \
    { x0 += x1; x1 = rotl32(x1,a); x1 ^= x0; \
      x0 += x1; x1 = rotl32(x1,b); x1 ^= x0; \
      x0 += x1; x1 = rotl32(x1,c); x1 ^= x0; \
      x0 += x1; x1 = rotl32(x1,d); x1 ^= x0; }
    TF_R4(13,15,26,6);  x0 += k1;  x1 += ks2 + 1u;
    TF_R4(17,29,16,24); x0 += ks2; x1 += k0  + 2u;
    TF_R4(13,15,26,6);  x0 += k0;  x1 += k1  + 3u;
    TF_R4(17,29,16,24); x0 += k1;  x1 += ks2 + 4u;
    TF_R4(13,15,26,6);  x0 += ks2; x1 += k0  + 5u;
#undef TF_R4
    return make_uint2(x0, x1);
}
// JAX partitionable random_bits (32-bit): xor-fold of both output lanes.
__device__ __forceinline__ uint32_t jax_random_bits32(uint32_t i) {
    uint2 o = threefry2x32(0u, 42u, 0u, i);
    return o.x ^ o.y;
}

// Branchless register top-8 insert (constant indices only; no local memory).
#define TOP8_INSERT(tv, ti, v, idx)                                   \
    {                                                                 \
        float _cv = (v); int _ci = (idx);                             \
        _Pragma("unroll")                                             \
        for (int _k = 0; _k < 8; _k++) {                              \
            bool _gt = _cv > tv[_k];                                  \
            float _ov = tv[_k]; int _oi = ti[_k];                     \
            tv[_k] = _gt ? _cv : tv[_k];                              \
            ti[_k] = _gt ? _ci : ti[_k];                              \
            _cv = _gt ? _ov : _cv;                                    \
            _ci = _gt ? _oi : _ci;                                    \
        }                                                             \
    }

// ---------------- kernel 1: fused row L2 normalize -> bf16 (emb + proj) ----------------
__global__ void normalize_kernel(const float* __restrict__ emb,
                                 const float* __restrict__ proj) {
    int b = blockIdx.x, tid = threadIdx.x;
    const float* src;
    __nv_bfloat16* dstb;
    int r;
    if (b < VPAD) {
        r = b;
        if (r >= V_REAL) {           // zero-pad rows
            ushort4 z; z.x = z.y = z.z = z.w = 0;
            ((ushort4*)(g_embn_bf16 + (size_t)r * EDIM))[tid] = z;
            return;
        }
        src = emb; dstb = g_embn_bf16;
    } else {
        r = b - VPAD;
        src = proj; dstb = g_projn_bf16;
    }
    float4 v = ((const float4*)(src + (size_t)r * EDIM))[tid];
    float ss = v.x * v.x + v.y * v.y + v.z * v.z + v.w * v.w;
    #pragma unroll
    for (int o = 16; o; o >>= 1) ss += __shfl_xor_sync(0xffffffffu, ss, o);
    __shared__ float wsum[4];
    if ((tid & 31) == 0) wsum[tid >> 5] = ss;
    __syncthreads();
    float tot = wsum[0] + wsum[1] + wsum[2] + wsum[3];
    float denom = fmaxf(sqrtf(tot), NORM_EPS);
    ushort4 bb;
    bb.x = __bfloat16_as_ushort(__float2bfloat16(v.x / denom));
    bb.y = __bfloat16_as_ushort(__float2bfloat16(v.y / denom));
    bb.z = __bfloat16_as_ushort(__float2bfloat16(v.z / denom));
    bb.w = __bfloat16_as_ushort(__float2bfloat16(v.w / denom));
    ((ushort4*)(dstb + (size_t)r * EDIM))[tid] = bb;
}

// ---------------- kernel 3: persistent bf16 MMA GEMM + carried top-8 (unchanged R16) ----------------
__global__ void __launch_bounds__(256, 2) gemm_topk_kernel() {
    extern __shared__ char smem[];
    const int tid = threadIdx.x, lane = tid & 31, wid = tid >> 5;
    const int grp = blockIdx.x, bm = blockIdx.y;
    const int m0 = bm * BM;
    const int ncol0 = grp * TPG * BN;

    uint32_t sbase = (uint32_t)__cvta_generic_to_shared(smem);
    float* sc = (float*)(smem + SC_OFF);          // [128][66] score staging

    const int wm0 = (wid >> 1) * 32;
    const int wn  = wid & 1;
    const int wn0 = wn * 64;

    auto loadChunk = [&](int c, int st) {
        int t = c >> 4, kc = c & 15;
        uint32_t aB = sbase + st * STAGE_BYTES;
        uint32_t bB = aB + 10240;
        const __nv_bfloat16* gp = g_projn_bf16 + (size_t)m0 * EDIM + kc * BK;
        const __nv_bfloat16* gb = g_embn_bf16 + (size_t)(ncol0 + t * BN) * EDIM + kc * BK;
        #pragma unroll
        for (int i = 0; i < 2; i++) {
            int vId = tid + i * 256;
            int row = vId >> 2, q = vId & 3;
            cp16(aB + (row * LDA + q * 8) * 2, gp + (size_t)row * EDIM + q * 8);
            cp16(bB + (row * LDB + q * 8) * 2, gb + (size_t)row * EDIM + q * 8);
        }
    };

    const int aRow = lane & 15;
    const int aK   = (lane >> 4) << 3;
    const int bN   = (lane & 7) + (((lane >> 4) & 1) << 3);
    const int bK   = ((lane >> 3) & 1) << 3;
    const int g    = lane >> 2, t4 = lane & 3;

    const int erow  = tid & 127;
    const int eoff  = (tid >> 7) * 32;

    float tv[TOPK]; int ti[TOPK];
    #pragma unroll
    for (int k = 0; k < TOPK; k++) { tv[k] = -FLT_MAX_; ti[k] = -1; }

    const int TOT = TPG * NKC;
    loadChunk(0, 0); cp_commit();
    loadChunk(1, 1); cp_commit();
    loadChunk(2, 2); cp_commit();

    for (int t = 0; t < TPG; t++) {
        float acc[2][8][4];
        #pragma unroll
        for (int mi = 0; mi < 2; mi++)
            #pragma unroll
            for (int ni = 0; ni < 8; ni++)
                #pragma unroll
                for (int q = 0; q < 4; q++) acc[mi][ni][q] = 0.f;

        for (int kc = 0; kc < NKC; kc++) {
            const int c = t * NKC + kc;
            if (c + 2 < TOT) cp_wait2(); else cp_wait0();
            __syncthreads();
            if (c + 3 < TOT) { loadChunk(c + 3, (c + 3) % NSTAGE); cp_commit(); }

            uint32_t aBase = sbase + (c % NSTAGE) * STAGE_BYTES;
            uint32_t bBase = aBase + 10240;
            #pragma unroll
            for (int s = 0; s < 2; s++) {
                uint32_t a[2][4], b[8][2];
                int k16 = s * 16;
                #pragma unroll
                for (int mi = 0; mi < 2; mi++) {
                    uint32_t addr = aBase + (((wm0 + mi * 16 + aRow) * LDA) + k16 + aK) * 2;
                    ldsm4(a[mi], addr);
                }
                #pragma unroll
                for (int p = 0; p < 4; p++) {
                    uint32_t tmp[4];
                    uint32_t addr = bBase + (((wn0 + p * 16 + bN) * LDB) + k16 + bK) * 2;
                    ldsm4(tmp, addr);
                    b[2 * p][0] = tmp[0]; b[2 * p][1] = tmp[1];
                    b[2 * p + 1][0] = tmp[2]; b[2 * p + 1][1] = tmp[3];
                }
                #pragma unroll
                for (int mi = 0; mi < 2; mi++)
                    #pragma unroll
                    for (int ni = 0; ni < 8; ni++)
                        mma16816(acc[mi][ni], a[mi], b[ni]);
            }
        }

        const int tile_col0 = ncol0 + t * BN;
        #pragma unroll
        for (int h = 0; h < 2; h++) {
            __syncthreads();
            if (wn == h) {
                #pragma unroll
                for (int mi = 0; mi < 2; mi++)
                    #pragma unroll
                    for (int ni = 0; ni < 8; ni++) {
                        int r = wm0 + mi * 16 + g;
                        int c = ni * 8 + t4 * 2;
                        sc[r * 66 + c]           = acc[mi][ni][0];
                        sc[r * 66 + c + 1]       = acc[mi][ni][1];
                        sc[(r + 8) * 66 + c]     = acc[mi][ni][2];
                        sc[(r + 8) * 66 + c + 1] = acc[mi][ni][3];
                    }
            }
            __syncthreads();
            {
                const float* rowp = sc + erow * 66 + eoff;
                int col0 = tile_col0 + h * 64 + eoff;
                #pragma unroll 8
                for (int c = 0; c < 32; c++) {
                    float v = rowp[c];
                    int col = col0 + c;
                    if (v > tv[TOPK - 1] && col < V_REAL) {
                        TOP8_INSERT(tv, ti, v, col);
                    }
                }
            }
        }
    }

    {
        float2* dst = g_cand + ((size_t)(m0 + erow) * GN + grp) * 16 + (tid >> 7) * 8;
        #pragma unroll
        for (int j = 0; j < TOPK; j++) dst[j] = make_float2(tv[j], __int_as_float(ti[j]));
    }
}

// ---------------- kernel 4: merge 144 candidates (warp argmax), rescore, sample ----------------
__global__ void __launch_bounds__(256) merge_sample_kernel(const float* __restrict__ proj_raw,
                                                           const float* __restrict__ emb_raw,
                                                           float* __restrict__ out) {
    __shared__ float sh_proj[EDIM];
    __shared__ float sv[160];          // 144 used, padded
    __shared__ int   si[160];
    __shared__ int   sidx[NSEL];
    __shared__ float strue[NSEL];
    __shared__ float pnorm2[8];

    const int row = blockIdx.x;
    const int tid = threadIdx.x, lane = tid & 31, wid = tid >> 5;

    // normalize raw projection row into sh_proj
    {
        float ss = 0.f;
        for (int j = tid; j < EDIM; j += 256) {
            float x = proj_raw[(size_t)row * EDIM + j];
            sh_proj[j] = x;
            ss += x * x;
        }
        #pragma unroll
        for (int o = 16; o; o >>= 1) ss += __shfl_xor_sync(0xffffffffu, ss, o);
        if (lane == 0) pnorm2[wid] = ss;
        __syncthreads();
        float tot = 0.f;
        #pragma unroll
        for (int w = 0; w < 8; w++) tot += pnorm2[w];
        float denom = fmaxf(sqrtf(tot), NORM_EPS);
        __syncthreads();
        for (int j = tid; j < EDIM; j += 256) sh_proj[j] = sh_proj[j] / denom;
    }
    if (tid < CAND) {
        float2 cv = g_cand[(size_t)row * CAND + tid];
        sv[tid] = cv.x; si[tid] = __float_as_int(cv.y);
    }
    __syncthreads();

    // warp 0 only: top-NSEL of 144 via register-resident iterative warp argmax
    if (wid == 0) {
        float v[5];
        #pragma unroll
        for (int k = 0; k < 5; k++) {
            int slot = lane + k * 32;
            v[k] = (slot < CAND) ? sv[slot] : -FLT_MAX_;
        }
        for (int it = 0; it < NSEL; it++) {
            // local argmax over 5 regs
            float bv = v[0]; int bk = 0;
            #pragma unroll
            for (int k = 1; k < 5; k++) { bool gt = v[k] > bv; bv = gt ? v[k] : bv; bk = gt ? k : bk; }
            int bpos = bk * 32 + lane;
            // warp reduce
            #pragma unroll
            for (int o = 16; o; o >>= 1) {
                float ov = __shfl_down_sync(0xffffffffu, bv, o);
                int   op = __shfl_down_sync(0xffffffffu, bpos, o);
                if (ov > bv) { bv = ov; bpos = op; }
            }
            bpos = __shfl_sync(0xffffffffu, bpos, 0);
            if (lane == 0) sidx[it] = si[bpos];
            // clear winner
            if ((bpos & 31) == lane) {
                int wk = bpos >> 5;
                #pragma unroll
                for (int k = 0; k < 5; k++) if (k == wk) v[k] = -FLT_MAX_;
            }
        }
    }
    __syncthreads();

    // exact fp32 rescore (float4 loads): s = <proj_n, emb[idx]> / max(||emb[idx]||, eps)
    for (int c = wid; c < NSEL; c += 8) {
        int idx = sidx[c];
        float s = 0.f, e2 = 0.f;
        if (idx >= 0) {
            const float4* e4 = (const float4*)(emb_raw + (size_t)idx * EDIM);
            const float4* p4 = (const float4*)sh_proj;
            #pragma unroll
            for (int k = 0; k < 4; k++) {
                float4 ev = __ldg(&e4[lane + k * 32]);
                float4 pv = p4[lane + k * 32];
                s  = fmaf(pv.x, ev.x, fmaf(pv.y, ev.y, fmaf(pv.z, ev.z, fmaf(pv.w, ev.w, s))));
                e2 = fmaf(ev.x, ev.x, fmaf(ev.y, ev.y, fmaf(ev.z, ev.z, fmaf(ev.w, ev.w, e2))));
            }
        }
        #pragma unroll
        for (int o = 16; o; o >>= 1) {
            s  += __shfl_xor_sync(0xffffffffu, s, o);
            e2 += __shfl_xor_sync(0xffffffffu, e2, o);
        }
        if (lane == 0) strue[c] = (idx >= 0) ? s / fmaxf(sqrtf(e2), NORM_EPS) : -FLT_MAX_;
    }
    __syncthreads();

    if (tid == 0) {
        // stable top-8: val desc, index asc (matches lax.top_k)
        float fv[TOPK]; int fi[TOPK];
        unsigned used = 0;
        for (int r = 0; r < TOPK; r++) {
            int best = -1; float bv = 0.f; int bi = 0;
            for (int c = 0; c < NSEL; c++) {
                if ((used >> c) & 1u) continue;
                float v = strue[c]; int ix = sidx[c];
                if (best < 0 || v > bv || (v == bv && ix < bi)) { best = c; bv = v; bi = ix; }
            }
            used |= 1u << best;
            fv[r] = bv; fi[r] = bi;
        }
        // gumbel-argmax sampling (partitionable threefry, xor-fold)
        float m = -FLT_MAX_; int arg = 0;
        #pragma unroll
        for (int k = 0; k < TOPK; k++) {
            unsigned i = (unsigned)row * TOPK + k;
            unsigned bits = jax_random_bits32(i);
            float f = __uint_as_float((bits >> 9) | 0x3f800000u) - 1.0f;
            float u = fmaxf(TINY_F, f);
            float gmb = -logf(-logf(u));
            float t = fv[k] + gmb;
            if (t > m) { m = t; arg = k; }
        }
        out[row] = (float)fi[arg];
    }
}

// ---------------- launcher ----------------
extern "C" void kernel_launch(void* const* d_in, const int* in_sizes, int n_in,
                              void* d_out, int out_size) {
    int ie = 0, ip = 0;
    long b1 = -1, b2 = -1;
    for (int i = 0; i < n_in; i++) {
        long s = in_sizes[i];
        if (s > b1)      { b2 = b1; ip = ie; b1 = s; ie = i; }
        else if (s > b2) { b2 = s; ip = i; }
    }
    const float* emb  = (const float*)d_in[ie];   // [50257,512]
    const float* proj = (const float*)d_in[ip];   // [4,1024,512]
    float* out = (float*)d_out;                   // [4,1024] float32 token ids

    cudaFuncSetAttribute(gemm_topk_kernel,
                         cudaFuncAttributeMaxDynamicSharedMemorySize, SMEM_GEMM);

    normalize_kernel<<<VPAD + MROWS, 128>>>(emb, proj);
    gemm_topk_kernel<<<dim3(GN, 32), 256, SMEM_GEMM>>>();
    merge_sample_kernel<<<MROWS, 256>>>(proj, emb, out);
}